// round 2
// baseline (speedup 1.0000x reference)
#include <cuda_runtime.h>
#include <cuda_bf16.h>
#include <cstdint>

// PatchExtractor3d (im2col for one-hot 3x3x3 conv, pad=1):
//   out[b, c*27 + k, d, h, w] = x_pad[b, c, d+i-1, h+j-1, w+l-1],  k = 9i+3j+l
//   x:   [2, 3, 32, 128, 128] fp32  (12.6 MB  -> L2-resident)
//   out: [2, 81, 32, 128, 128] fp32 (340 MB   -> DRAM write bound)
//
// Layout: warp = one 128-float output row (lane = one aligned float4 quad,
// WQ = 32 = warp size). Each warp processes 8 consecutive h-rows of the same
// (bc, k, d) so the index decompose is amortized. The +-1 width shifts for
// l=0 / l=2 are assembled from the lane's aligned quad plus ONE shuffled
// neighbor element, so every load is an aligned LDG.128 and every store an
// aligned STG.128 — no scalar loads, no divergence (l is warp-uniform).

static constexpr int B = 2, C = 3, D = 32, H = 128, W = 128;
static constexpr int WQ = W / 4;                  // 32 quads per row = warp size
static constexpr int ROWS_PER_WARP   = 8;
static constexpr int WARPS_PER_BLOCK = 8;
static constexpr int THREADS = WARPS_PER_BLOCK * 32;          // 256
static constexpr int HGROUPS = H / ROWS_PER_WARP;             // 16
static constexpr int TOTAL_GROUPS = B * C * 27 * D * HGROUPS; // 82,944
static constexpr int BLOCKS = TOTAL_GROUPS / WARPS_PER_BLOCK; // 10,368

__global__ __launch_bounds__(THREADS)
void patch3d_kernel(const float* __restrict__ x, float4* __restrict__ out) {
    const int wid  = threadIdx.x >> 5;
    const int lane = threadIdx.x & 31;
    const int g    = blockIdx.x * WARPS_PER_BLOCK + wid;

    // g = (((bc*27 + k)*D + d)*HGROUPS + hg   — all warp-uniform
    const int hg   = g & (HGROUPS - 1);       // 4 bits
    const int d    = (g >> 4) & (D - 1);      // 5 bits
    const int rest = g >> 9;                  // 0 .. 161
    const int k    = rest % 27;
    const int bc   = rest / 27;

    const int i = k / 9;
    const int j = (k - 9 * i) / 3;
    const int l = k - 9 * i - 3 * j;          // width shift index, warp-uniform

    const int zs = d + i - 1;                 // source depth (fixed per warp)
    const int h0 = hg * ROWS_PER_WARP;

    float4* __restrict__ orow =
        out + (((((bc * 27 + k) * D + d) * H + h0)) * WQ) + lane;
    const float4 zero = make_float4(0.f, 0.f, 0.f, 0.f);

    if ((unsigned)zs >= (unsigned)D) {
        // whole 8-row strip sources from depth padding -> zeros
        #pragma unroll
        for (int t = 0; t < ROWS_PER_WARP; t++) orow[t * WQ] = zero;
        return;
    }

    // source row pointer for t=0 (may point one row OOB when hs<0; never
    // dereferenced in that case — guarded below)
    const float4* __restrict__ xrow = reinterpret_cast<const float4*>(
        x + ((long long)(bc * D + zs) * H + (h0 + j - 1)) * W) + lane;

    #pragma unroll
    for (int t = 0; t < ROWS_PER_WARP; t++) {
        const int hs = h0 + t + j - 1;        // warp-uniform
        float4 v = zero;
        if ((unsigned)hs < (unsigned)H) {
            const float4 c = xrow[t * WQ];
            if (l == 1) {
                v = c;                                        // aligned copy
            } else if (l == 0) {
                // out[w] = x[w-1]: (prev.w, c.x, c.y, c.z), lane0 left edge = 0
                float lw = __shfl_up_sync(0xffffffffu, c.w, 1);
                v = make_float4(lane == 0 ? 0.f : lw, c.x, c.y, c.z);
            } else {
                // out[w] = x[w+1]: (c.y, c.z, c.w, next.x), lane31 right edge = 0
                float rx = __shfl_down_sync(0xffffffffu, c.x, 1);
                v = make_float4(c.y, c.z, c.w, lane == 31 ? 0.f : rx);
            }
        }
        orow[t * WQ] = v;
    }
}

extern "C" void kernel_launch(void* const* d_in, const int* in_sizes, int n_in,
                              void* d_out, int out_size) {
    const float* x = (const float*)d_in[0];
    patch3d_kernel<<<BLOCKS, THREADS>>>(x, (float4*)d_out);
}

// round 4
// speedup vs baseline: 1.0115x; 1.0115x over previous
#include <cuda_runtime.h>
#include <cuda_bf16.h>
#include <cstdint>

// PatchExtractor3d (im2col for one-hot 3x3x3 conv, pad=1):
//   out[b, c*27 + k, d, h, w] = x_pad[b, c, d+i-1, h+j-1, w+l-1],  k = 9i+3j+l
//   x:   [2, 3, 32, 128, 128] fp32  (12.6 MB, L2-resident)
//   out: [2, 81, 32, 128, 128] fp32 (340 MB, DRAM write bound)
//
// Key change vs the 62.1us version: one CTA now produces ALL 27 k-variants of
// one (bc, d, 8-row h-strip). Each warp (t = wid = row within strip) loads its
// 9 distinct source rows (3 depths x 3 h-shifts) ONCE via aligned LDG.128 —
// repeats across the CTA hit L1 — and fans each into the 3 width shifts
// (l=0: shuffle-up, l=1: direct, l=2: shuffle-down) as aligned STG.128.
// This removes the 27x L2 read amplification (680 MB -> ~386 MB of LTS
// traffic), moving the bottleneck from the L2 cap to the DRAM write floor.

static constexpr int B = 2, C = 3, D = 32, H = 128, W = 128;
static constexpr int WQ = W / 4;                   // 32 quads/row = warp size
static constexpr int ROWS_PER_CTA = 8;             // warp t -> row h0+t
static constexpr int HGROUPS = H / ROWS_PER_CTA;   // 16
static constexpr int THREADS = ROWS_PER_CTA * 32;  // 256
static constexpr int BLOCKS  = B * C * D * HGROUPS;        // 3072
static constexpr int KSTRIDE = D * H * WQ;                 // quads per k step

__global__ __launch_bounds__(THREADS)
void patch3d_kernel(const float* __restrict__ x, float4* __restrict__ out) {
    const int wid  = threadIdx.x >> 5;    // row-within-strip, warp-uniform
    const int lane = threadIdx.x & 31;

    // blockIdx.x = (bc*D + d)*HGROUPS + hg
    const int g  = blockIdx.x;
    const int hg = g & (HGROUPS - 1);     // 4 bits
    const int d  = (g >> 4) & (D - 1);    // 5 bits
    const int bc = g >> 9;                // 0..5
    const int h  = hg * ROWS_PER_CTA + wid;

    const float4 zero = make_float4(0.f, 0.f, 0.f, 0.f);
    const unsigned full = 0xffffffffu;

    // output quad pointer for k=0 at this (bc, d, h)
    float4* __restrict__ obase =
        out + (((bc * 27) * D + d) * H + h) * WQ + lane;

    #pragma unroll
    for (int i = 0; i < 3; i++) {
        const int zs = d + i - 1;                       // source depth
        const bool vz = (unsigned)zs < (unsigned)D;
        #pragma unroll
        for (int j = 0; j < 3; j++) {
            const int hs = h + j - 1;                   // source row (warp-uniform)
            float4 c = zero;
            if (vz && (unsigned)hs < (unsigned)H) {
                c = *(reinterpret_cast<const float4*>(
                        x + ((bc * D + zs) * H + hs) * W) + lane);
            }
            // three width shifts from one register quad
            const float lw = __shfl_up_sync(full, c.w, 1);
            const float rx = __shfl_down_sync(full, c.x, 1);
            const float4 v0 = make_float4(lane == 0  ? 0.f : lw, c.x, c.y, c.z);
            const float4 v2 = make_float4(c.y, c.z, c.w, lane == 31 ? 0.f : rx);

            const int k0 = 9 * i + 3 * j;
            obase[(k0 + 0) * KSTRIDE] = v0;   // l = 0: out[w] = x[w-1]
            obase[(k0 + 1) * KSTRIDE] = c;    // l = 1: aligned copy
            obase[(k0 + 2) * KSTRIDE] = v2;   // l = 2: out[w] = x[w+1]
        }
    }
}

extern "C" void kernel_launch(void* const* d_in, const int* in_sizes, int n_in,
                              void* d_out, int out_size) {
    const float* x = (const float*)d_in[0];
    patch3d_kernel<<<BLOCKS, THREADS>>>(x, (float4*)d_out);
}

// round 5
// speedup vs baseline: 1.1665x; 1.1532x over previous
#include <cuda_runtime.h>
#include <cuda_bf16.h>
#include <cstdint>

// PatchExtractor3d (im2col for one-hot 3x3x3 conv, pad=1):
//   out[b, c*27 + k, d, h, w] = x_pad[b, c, d+i-1, h+j-1, w+l-1],  k = 9i+3j+l
//   x:   [2, 3, 32, 128, 128] fp32  (12.6 MB, should stay L2-resident)
//   out: [2, 81, 32, 128, 128] fp32 (340 MB, DRAM write bound)
//
// R4 ncu: DRAM 62.7% *active* (idle 37%) with nothing else saturated -> feed
// problem, not bandwidth problem. This round:
//   1) PREFETCH all 9 source quads (3 depths x 3 h-shifts) into registers
//      before any shuffle/store -> 9 outstanding LDG.128 per warp (MLP 9)
//      instead of a serialized LDG->SHFL->STG chain per iteration.
//   2) __stcs (evict-first) on all output stores: output is write-once, so
//      keep the 340 MB write stream from thrashing the L2-resident input.
// CTA still produces all 27 k-variants of one (bc, d, 8-row strip), so input
// reads keep their L1/L2 reuse (no 27x read amplification).

static constexpr int B = 2, C = 3, D = 32, H = 128, W = 128;
static constexpr int WQ = W / 4;                   // 32 quads/row = warp size
static constexpr int ROWS_PER_CTA = 8;             // warp t -> row h0+t
static constexpr int HGROUPS = H / ROWS_PER_CTA;   // 16
static constexpr int THREADS = ROWS_PER_CTA * 32;  // 256
static constexpr int BLOCKS  = B * C * D * HGROUPS;        // 3072
static constexpr int KSTRIDE = D * H * WQ;                 // quads per k step

__global__ __launch_bounds__(THREADS)
void patch3d_kernel(const float* __restrict__ x, float4* __restrict__ out) {
    const int wid  = threadIdx.x >> 5;    // row-within-strip, warp-uniform
    const int lane = threadIdx.x & 31;

    // blockIdx.x = (bc*D + d)*HGROUPS + hg  (hg fastest: concurrent CTAs
    // write adjacent 4KB chunks of each of the 27 output streams)
    const int g  = blockIdx.x;
    const int hg = g & (HGROUPS - 1);     // 4 bits
    const int d  = (g >> 4) & (D - 1);    // 5 bits
    const int bc = g >> 9;                // 0..5
    const int h  = hg * ROWS_PER_CTA + wid;

    const float4 zero = make_float4(0.f, 0.f, 0.f, 0.f);
    const unsigned full = 0xffffffffu;

    // ---- Phase 1: prefetch the 9 source quads (independent LDG.128s) ----
    float4 r[9];
    #pragma unroll
    for (int i = 0; i < 3; i++) {
        const int zs = d + i - 1;
        const bool vz = (unsigned)zs < (unsigned)D;
        #pragma unroll
        for (int j = 0; j < 3; j++) {
            const int hs = h + j - 1;                 // warp-uniform
            float4 c = zero;
            if (vz && (unsigned)hs < (unsigned)H) {
                c = __ldg(reinterpret_cast<const float4*>(
                        x + ((bc * D + zs) * H + hs) * W) + lane);
            }
            r[3 * i + j] = c;
        }
    }

    // ---- Phase 2: fan each quad into 3 width shifts, streaming stores ----
    float4* __restrict__ obase =
        out + (((bc * 27) * D + d) * H + h) * WQ + lane;

    #pragma unroll
    for (int m = 0; m < 9; m++) {
        const float4 c = r[m];
        const float lw = __shfl_up_sync(full, c.w, 1);
        const float rx = __shfl_down_sync(full, c.x, 1);
        const float4 v0 = make_float4(lane == 0  ? 0.f : lw, c.x, c.y, c.z);
        const float4 v2 = make_float4(c.y, c.z, c.w, lane == 31 ? 0.f : rx);

        float4* p = obase + (3 * m) * KSTRIDE;
        __stcs(p,               v0);   // l = 0: out[w] = x[w-1]
        __stcs(p + KSTRIDE,     c);    // l = 1: aligned copy
        __stcs(p + 2 * KSTRIDE, v2);   // l = 2: out[w] = x[w+1]
    }
}

extern "C" void kernel_launch(void* const* d_in, const int* in_sizes, int n_in,
                              void* d_out, int out_size) {
    const float* x = (const float*)d_in[0];
    patch3d_kernel<<<BLOCKS, THREADS>>>(x, (float4*)d_out);
}